// round 5
// baseline (speedup 1.0000x reference)
#include <cuda_runtime.h>
#include <math.h>

// dims: (1,1,D=160,H=192,W=160), x fastest
#define DW 160
#define DH 192
#define DD 160
#define SLICE (DH*DW)
#define NVOX (DD*SLICE)

#define TX 32
#define TY 8
#define CZ 16
#define SMW (TX+2)
#define SMH (TY+2)
#define NTHREADS (TX*TY)
#define GXD (DW/TX)   // 5
#define GYD (DH/TY)   // 24
#define GZD (DD/CZ)   // 10
#define NBLOCKS (GXD*GYD*GZD)   // 1200
#define FEPS 1e-10f

__device__ float g_partial[NBLOCKS];
__device__ unsigned int g_count = 0;

// minimax atan: odd poly on [0,1], reciprocal fold for |x|>1. max err ~2e-6 rad.
__device__ __forceinline__ float fast_atanf(float x)
{
    const float ax = fabsf(x);
    const bool inv = ax > 1.0f;
    const float t = inv ? __fdividef(1.0f, ax) : ax;
    const float z = t * t;
    float p = -0.0117212f;
    p = fmaf(p, z, 0.05265332f);
    p = fmaf(p, z, -0.11643287f);
    p = fmaf(p, z, 0.19354346f);
    p = fmaf(p, z, -0.33262347f);
    p = fmaf(p, z, 0.99997726f);
    p = p * t;
    const float r = inv ? (1.5707963267948966f - p) : p;
    return copysignf(r, x);
}

// ZG = true only for z-edge block layers (blockIdx.z == 0 or GZD-1)
template<bool ZG>
__device__ __forceinline__ float run_tile(
    const float* __restrict__ Mp, const float* __restrict__ Sp,
    const float* __restrict__ Fp, float2 sm[2][SMH][SMW])
{
    const int tx = threadIdx.x, ty = threadIdx.y;
    const int tid = ty * TX + tx;
    const int x = blockIdx.x * TX + tx;
    const int y = blockIdx.y * TY + ty;
    const int zbase = blockIdx.z * CZ;

    // halo mapping (z-invariant): each thread covers <=2 of 340 slots
    const int ly0 = tid / SMW, lx0 = tid - ly0 * SMW;
    const int gy0 = blockIdx.y * TY + ly0 - 1;
    const int gx0 = blockIdx.x * TX + lx0 - 1;
    const bool v0 = ((unsigned)gy0 < (unsigned)DH) && ((unsigned)gx0 < (unsigned)DW);
    const int off0 = v0 ? (gy0 * DW + gx0) : 0;

    const int i1 = tid + NTHREADS;
    const bool has1 = (i1 < SMH * SMW);
    const int ly1 = i1 / SMW, lx1 = i1 - ly1 * SMW;
    const int gy1 = blockIdx.y * TY + ly1 - 1;
    const int gx1 = blockIdx.x * TX + lx1 - 1;
    const bool v1 = has1 && ((unsigned)gy1 < (unsigned)DH) && ((unsigned)gx1 < (unsigned)DW);
    const int off1 = v1 ? (gy1 * DW + gx1) : 0;

    // incremental pointers for M/S halo loads
    const float* pM0 = Mp + (zbase - 1) * SLICE + off0;
    const float* pS0 = Sp + (zbase - 1) * SLICE + off0;
    const float* pM1 = Mp + (zbase - 1) * SLICE + off1;
    const float* pS1 = Sp + (zbase - 1) * SLICE + off1;

    // depth-2 M/S pipeline preload: slices zbase-1, zbase
    float Pm0, Ps0, Pm1, Ps1, Qm0, Qs0, Qm1, Qs1;
    {
        const bool zin = !ZG || (zbase - 1 >= 0);
        Pm0 = (v0 && zin) ? __ldg(pM0) : 0.f;
        Ps0 = (v0 && zin) ? __ldg(pS0) : 0.f;
        Pm1 = (v1 && zin) ? __ldg(pM1) : 0.f;
        Ps1 = (v1 && zin) ? __ldg(pS1) : 0.f;
        pM0 += SLICE; pS0 += SLICE; pM1 += SLICE; pS1 += SLICE;
        Qm0 = v0 ? __ldg(pM0) : 0.f;
        Qs0 = v0 ? __ldg(pS0) : 0.f;
        Qm1 = v1 ? __ldg(pM1) : 0.f;
        Qs1 = v1 ? __ldg(pS1) : 0.f;
        pM0 += SLICE; pS0 += SLICE; pM1 += SLICE; pS1 += SLICE;
    }

    // depth-2 flow pipeline preload: z = zbase (emit j=2), zbase+1 (emit j=3)
    // flow z range [zbase, zbase+CZ-1] is always in-bounds — no guards.
    const float* pF = Fp + zbase * SLICE + y * DW + x;
    float Pfx = __ldg(pF), Pfy = __ldg(pF + NVOX), Pfz = __ldg(pF + 2 * NVOX);
    pF += SLICE;
    float Qfx = __ldg(pF), Qfy = __ldg(pF + NVOX), Qfz = __ldg(pF + 2 * NVOX);
    pF += SLICE;

    // per-slice separable responses, register ring of 3
    float AM0, AM1, AM2, BM0, BM1, BM2, CM0, CM1, CM2, Mc1, Mc2;
    float AS0, AS1, AS2, BS0, BS1, BS2, CS0, CS1, CS2, Sc1, Sc2;
    AM0=AM1=BM0=BM1=CM0=CM1=Mc1=0.f;
    AS0=AS1=BS0=BS1=CS0=CS1=Sc1=0.f;
    float acc = 0.f;

    #pragma unroll 2
    for (int j = 0; j <= CZ + 1; ++j) {
        const int b = j & 1;

        // commit slice (zbase-1+j) to smem
        sm[b][ly0][lx0] = make_float2(Pm0, Ps0);
        if (has1) sm[b][ly1][lx1] = make_float2(Pm1, Ps1);

        // rotate, issue load for slice zbase+j+1 (consumed 2 iters later)
        Pm0 = Qm0; Ps0 = Qs0; Pm1 = Qm1; Ps1 = Qs1;
        if (j <= CZ - 1) {
            const bool zin = !ZG || (zbase + j + 1 < DD);
            Qm0 = (v0 && zin) ? __ldg(pM0) : 0.f;
            Qs0 = (v0 && zin) ? __ldg(pS0) : 0.f;
            Qm1 = (v1 && zin) ? __ldg(pM1) : 0.f;
            Qs1 = (v1 && zin) ? __ldg(pS1) : 0.f;
            pM0 += SLICE; pS0 += SLICE; pM1 += SLICE; pS1 += SLICE;
        }
        __syncthreads();

        // in-plane separable responses (float2: M=.x, S=.y)
        const float2 a0 = sm[b][ty + 0][tx], a1 = sm[b][ty + 0][tx + 1], a2 = sm[b][ty + 0][tx + 2];
        const float2 q0 = sm[b][ty + 1][tx], q1 = sm[b][ty + 1][tx + 1], q2 = sm[b][ty + 1][tx + 2];
        const float2 c0 = sm[b][ty + 2][tx], c1 = sm[b][ty + 2][tx + 1], c2 = sm[b][ty + 2][tx + 2];

        {   // M
            const float rD0 = a2.x - a0.x, rSm0 = fmaf(2.f, a1.x, a0.x + a2.x), rB0 = a0.x + a1.x + a2.x;
            const float rD1 = q2.x - q0.x,                                      rB1 = q0.x + q1.x + q2.x;
            const float rD2 = c2.x - c0.x, rSm2 = fmaf(2.f, c1.x, c0.x + c2.x), rB2 = c0.x + c1.x + c2.x;
            AM2 = fmaf(2.f, rD1, rD0 + rD2);
            BM2 = rSm2 - rSm0;
            CM2 = fmaf(2.f, rB1, rB0 + rB2);
            Mc2 = q1.x;
        }
        {   // S
            const float rD0 = a2.y - a0.y, rSm0 = fmaf(2.f, a1.y, a0.y + a2.y), rB0 = a0.y + a1.y + a2.y;
            const float rD1 = q2.y - q0.y,                                      rB1 = q0.y + q1.y + q2.y;
            const float rD2 = c2.y - c0.y, rSm2 = fmaf(2.f, c1.y, c0.y + c2.y), rB2 = c0.y + c1.y + c2.y;
            AS2 = fmaf(2.f, rD1, rD0 + rD2);
            BS2 = rSm2 - rSm0;
            CS2 = fmaf(2.f, rB1, rB0 + rB2);
            Sc2 = q1.y;
        }

        // emit output voxel z = zbase + j - 2 once three slices are live
        if (j >= 2) {
            const float Mx = AM0 + AM1 + AM2;
            const float My = BM0 + BM1 + BM2;
            const float Mz = CM2 - CM0;
            const float Sx = AS0 + AS1 + AS2;
            const float Sy = BS0 + BS1 + BS2;
            const float Sz = CS2 - CS0;

            const float Id  = Mc1 - Sc1;
            const float Id2 = fmaf(Id, Id, FEPS);
            const float dS = fmaf(Sx, Sx, fmaf(Sy, Sy, fmaf(Sz, Sz, Id2)));
            const float dM = fmaf(Mx, Mx, fmaf(My, My, fmaf(Mz, Mz, Id2)));
            const float invS = __fdividef(1.f, dS);
            const float invM = __fdividef(1.f, dM);
            const float Ux = Id * fmaf(Sx, invS, Mx * invM);
            const float Uy = Id * fmaf(Sy, invS, My * invM);
            const float Uz = Id * fmaf(Sz, invS, Mz * invM);

            const float izd = __fdividef(1.f, Uz + FEPS);
            const float dxz = fast_atanf(Ux * izd);
            const float dyz = fast_atanf(Uy * izd);

            const float ifz = __fdividef(1.f, Pfz + FEPS);
            const float fxz = fast_atanf(Pfx * ifz);
            const float fyz = fast_atanf(Pfy * ifz);

            const float e1 = fxz - dxz;
            const float e2 = fyz - dyz;
            acc = fmaf(e1, e1, acc);
            acc = fmaf(e2, e2, acc);

            // rotate flow pipeline; load F for z = zbase+j (emit at j+2)
            Pfx = Qfx; Pfy = Qfy; Pfz = Qfz;
            if (j <= CZ - 1) {
                Qfx = __ldg(pF);
                Qfy = __ldg(pF + NVOX);
                Qfz = __ldg(pF + 2 * NVOX);
                pF += SLICE;
            }
        }

        // shift register rings
        AM0 = AM1; AM1 = AM2;  BM0 = BM1; BM1 = BM2;
        CM0 = CM1; CM1 = CM2;  Mc1 = Mc2;
        AS0 = AS1; AS1 = AS2;  BS0 = BS1; BS1 = BS2;
        CS0 = CS1; CS1 = CS2;  Sc1 = Sc2;
    }
    return acc;
}

__global__ __launch_bounds__(NTHREADS, 4)
void demons_kernel(const float* __restrict__ Mp,
                   const float* __restrict__ Sp,
                   const float* __restrict__ Fp,
                   float* __restrict__ out)
{
    __shared__ float2 sm[2][SMH][SMW];
    __shared__ float warpred[NTHREADS / 32];
    __shared__ bool isLast;

    const int tid = threadIdx.y * TX + threadIdx.x;
    const int bid = blockIdx.x + GXD * (blockIdx.y + GYD * blockIdx.z);

    const bool zedge = (blockIdx.z == 0) || (blockIdx.z == GZD - 1);
    float acc = zedge ? run_tile<true>(Mp, Sp, Fp, sm)
                      : run_tile<false>(Mp, Sp, Fp, sm);

    // block reduction: warp shuffle + smem
    #pragma unroll
    for (int o = 16; o > 0; o >>= 1) acc += __shfl_xor_sync(0xffffffffu, acc, o);
    if ((tid & 31) == 0) warpred[tid >> 5] = acc;
    __syncthreads();
    if (tid == 0) {
        float v = 0.f;
        #pragma unroll
        for (int w = 0; w < NTHREADS / 32; ++w) v += warpred[w];
        g_partial[bid] = v;
        __threadfence();
        const unsigned int c = atomicAdd(&g_count, 1u);
        isLast = (c == (unsigned)(NBLOCKS - 1));
    }
    __syncthreads();

    // last block reduces partials, writes scalar, resets counter
    if (isLast) {
        float s = 0.f;
        for (int i = tid; i < NBLOCKS; i += NTHREADS) s += g_partial[i];
        #pragma unroll
        for (int o = 16; o > 0; o >>= 1) s += __shfl_xor_sync(0xffffffffu, s, o);
        if ((tid & 31) == 0) warpred[tid >> 5] = s;
        __syncthreads();
        if (tid == 0) {
            float t = 0.f;
            #pragma unroll
            for (int w = 0; w < NTHREADS / 32; ++w) t += warpred[w];
            out[0] = t / (float)NVOX;
            g_count = 0u;
        }
    }
}

extern "C" void kernel_launch(void* const* d_in, const int* in_sizes, int n_in,
                              void* d_out, int out_size)
{
    const float* Mp = (const float*)d_in[0];
    const float* Sp = (const float*)d_in[1];
    const float* Fp = (const float*)d_in[2];
    float* out = (float*)d_out;

    dim3 grid(GXD, GYD, GZD);   // (5, 24, 10) = 1200 blocks
    dim3 block(TX, TY, 1);      // (32, 8)
    demons_kernel<<<grid, block>>>(Mp, Sp, Fp, out);
}